// round 3
// baseline (speedup 1.0000x reference)
#include <cuda_runtime.h>

#define NMAX 100000
#define HID 256
#define EMB 128

#define QS 65535.0f
#define QI 1.5259021896696422e-05f   // 1/65535

// ---------------- scratch (static device globals; no allocation) -------------
__device__ int            g_degi[NMAX];            // degree incl. self loop
__device__ unsigned short g_disq[NMAX];            // dis quantized to u16 (scale 65535)
__device__ unsigned int   g_tq[NMAX];              // integer sum of quantized dis[src]
__device__ float          g_thr[HID];              // sorted relu breakpoints
__device__ __align__(16) float2 g_tab[(HID + 1) * EMB]; // per-interval (A, C)
__device__ int            g_e32;                   // 1 if edge_index is int32-packed

// ---- K1: init deg/tq; last block: detect edge dtype + sort relu thresholds --
__global__ void k_init(const void* __restrict__ edges,
                       const float* __restrict__ W1, const float* __restrict__ b1,
                       int N) {
    if (blockIdx.x == gridDim.x - 1) {
        int t = threadIdx.x;
        if (t == 0) {
            const long long* p = (const long long*)edges;
            int is32 = 0;
            #pragma unroll
            for (int i = 0; i < 4; i++)
                if ((unsigned long long)p[i] >= (1ull << 32)) is32 = 1;
            g_e32 = is32;
        }
        // relu(s*w+b) crossing for s>0: thr=-b/w if (w>0,b<0) or (w<0,b>0)
        __shared__ float key[HID];
        float w = W1[t], b = b1[t];
        float thr = 3.0e38f;
        if ((w > 0.f && b < 0.f) || (w < 0.f && b > 0.f)) thr = -b / w;
        key[t] = thr;
        __syncthreads();
        for (int k = 2; k <= HID; k <<= 1) {
            for (int j = k >> 1; j > 0; j >>= 1) {
                int p = t ^ j;
                if (p > t) {
                    bool up = ((t & k) == 0);
                    float ka = key[t], kb = key[p];
                    if ((ka > kb) == up) { key[t] = kb; key[p] = ka; }
                }
                __syncthreads();
            }
        }
        g_thr[t] = key[t];
    } else {
        int n = blockIdx.x * blockDim.x + threadIdx.x;
        if (n < N) { g_degi[n] = 1; g_tq[n] = 0u; }
    }
}

// ---- K2: degree over dst (8 edges / thread, streaming int4 loads) -----------
__global__ void k_deg(const void* __restrict__ edges, int E) {
    int i = (blockIdx.x * blockDim.x + threadIdx.x) * 8;
    if (i >= E) return;
    if (g_e32) {
        const int* p = (const int*)edges + E;  // dst half
        if (i + 8 <= E) {
            const int4* q = (const int4*)(p + i);
            int4 a = __ldcs(q);
            int4 b = __ldcs(q + 1);
            atomicAdd(&g_degi[a.x], 1); atomicAdd(&g_degi[a.y], 1);
            atomicAdd(&g_degi[a.z], 1); atomicAdd(&g_degi[a.w], 1);
            atomicAdd(&g_degi[b.x], 1); atomicAdd(&g_degi[b.y], 1);
            atomicAdd(&g_degi[b.z], 1); atomicAdd(&g_degi[b.w], 1);
        } else {
            for (int j = i; j < E; j++) atomicAdd(&g_degi[p[j]], 1);
        }
    } else {
        const long long* p = (const long long*)edges + E;
        if (i + 8 <= E) {
            const int4* q = (const int4*)(p + i);
            int4 a = __ldcs(q), b = __ldcs(q + 1), c = __ldcs(q + 2), d = __ldcs(q + 3);
            atomicAdd(&g_degi[a.x], 1); atomicAdd(&g_degi[a.z], 1);
            atomicAdd(&g_degi[b.x], 1); atomicAdd(&g_degi[b.z], 1);
            atomicAdd(&g_degi[c.x], 1); atomicAdd(&g_degi[c.z], 1);
            atomicAdd(&g_degi[d.x], 1); atomicAdd(&g_degi[d.z], 1);
        } else {
            for (int j = i; j < E; j++) atomicAdd(&g_degi[(int)p[j]], 1);
        }
    }
}

// ---- K3: quantize dis to u16 (L1-resident gather table for k_scat) ----------
__global__ void k_dis(int N) {
    int n = blockIdx.x * blockDim.x + threadIdx.x;
    if (n < N)
        g_disq[n] = (unsigned short)__float2uint_rn(rsqrtf((float)g_degi[n]) * QS);
}

// ---- K4: build tables, one block per interval (257 blocks x 128 threads) ----
__global__ void k_tab(const float* __restrict__ W1, const float* __restrict__ b1,
                      const float* __restrict__ W2, const float* __restrict__ b2) {
    __shared__ float sw[HID], sb[HID];
    int j = threadIdx.x;
    int k = blockIdx.x;
    sw[j] = W1[j]; sw[j + 128] = W1[j + 128];
    sb[j] = b1[j]; sb[j + 128] = b1[j + 128];
    __syncthreads();

    float lo = (k == 0) ? 0.f : g_thr[k - 1];
    float hi = (k == HID) ? ((lo < 1e30f) ? fmaf(2.f, lo, 2.f) : 3.2e38f) : g_thr[k];
    float rep = 0.5f * lo + 0.5f * hi;

    float a = 0.f, c = b2[j];
    #pragma unroll 4
    for (int h = 0; h < HID; h++) {
        float w = sw[h], b = sb[h];
        if (fmaf(rep, w, b) > 0.f) {
            float w2 = __ldg(&W2[h * EMB + j]);
            a = fmaf(w, w2, a);
            c = fmaf(b, w2, c);
        }
    }
    g_tab[k * EMB + j] = make_float2(a, c);
}

// ---- K5: tq[dst] += disq[src]  (u16 L1 gather + u32 L2 atomic, no float) ----
__device__ __forceinline__ void scat1(int src, int dst) {
    unsigned int q = (unsigned int)__ldg(&g_disq[src]);
    atomicAdd(&g_tq[dst], q);
}
__global__ void k_scat(const void* __restrict__ edges, int E) {
    int i = (blockIdx.x * blockDim.x + threadIdx.x) * 8;
    if (i >= E) return;
    if (g_e32) {
        const int* ps = (const int*)edges;
        const int* pd = ps + E;
        if (i + 8 <= E) {
            const int4* qs = (const int4*)(ps + i);
            const int4* qd = (const int4*)(pd + i);
            int4 s0 = __ldcs(qs), s1 = __ldcs(qs + 1);
            int4 d0 = __ldcs(qd), d1 = __ldcs(qd + 1);
            scat1(s0.x, d0.x); scat1(s0.y, d0.y); scat1(s0.z, d0.z); scat1(s0.w, d0.w);
            scat1(s1.x, d1.x); scat1(s1.y, d1.y); scat1(s1.z, d1.z); scat1(s1.w, d1.w);
        } else {
            for (int j = i; j < E; j++) scat1(ps[j], pd[j]);
        }
    } else {
        const long long* ps = (const long long*)edges;
        const long long* pd = ps + E;
        if (i + 8 <= E) {
            const int4* qs = (const int4*)(ps + i);
            const int4* qd = (const int4*)(pd + i);
            int4 s0 = __ldcs(qs), s1 = __ldcs(qs + 1), s2 = __ldcs(qs + 2), s3 = __ldcs(qs + 3);
            int4 d0 = __ldcs(qd), d1 = __ldcs(qd + 1), d2 = __ldcs(qd + 2), d3 = __ldcs(qd + 3);
            scat1(s0.x, d0.x); scat1(s0.z, d0.z);
            scat1(s1.x, d1.x); scat1(s1.z, d1.z);
            scat1(s2.x, d2.x); scat1(s2.z, d2.z);
            scat1(s3.x, d3.x); scat1(s3.z, d3.z);
        } else {
            for (int j = i; j < E; j++) scat1((int)ps[j], (int)pd[j]);
        }
    }
}

// ---- K6: per-node s + binary search + 128 affine sigmoids (2 nodes/thread) --
__global__ void k_out(float* __restrict__ out, int N) {
    __shared__ float sthr[HID];
    for (int i = threadIdx.x; i < HID; i += blockDim.x) sthr[i] = g_thr[i];
    __syncthreads();

    int n0 = (blockIdx.x * blockDim.x + threadIdx.x) * 2;
    if (n0 >= N) return;
    bool has2 = (n0 + 1 < N) && ((N & 1) == 0);
    int n1 = has2 ? n0 + 1 : n0;

    float d0 = rsqrtf((float)g_degi[n0]);
    float d1 = rsqrtf((float)g_degi[n1]);
    float s0 = d0 * ((float)g_tq[n0] * QI + d0);
    float s1 = d1 * ((float)g_tq[n1] * QI + d1);

    int lo0 = 0, hi0 = HID, lo1 = 0, hi1 = HID;
    #pragma unroll
    for (int it = 0; it < 8; it++) {
        int m0 = (lo0 + hi0) >> 1;
        if (sthr[m0] < s0) lo0 = m0 + 1; else hi0 = m0;
        int m1 = (lo1 + hi1) >> 1;
        if (sthr[m1] < s1) lo1 = m1 + 1; else hi1 = m1;
    }

    const float4* __restrict__ r0 = (const float4*)(g_tab + lo0 * EMB);
    const float4* __restrict__ r1 = (const float4*)(g_tab + lo1 * EMB);

    if (has2) {
        #pragma unroll 8
        for (int jj = 0; jj < EMB / 2; jj++) {
            float4 va = __ldg(&r0[jj]);
            float4 vb = __ldg(&r1[jj]);
            float xa0 = fmaf(s0, va.x, va.y), xa1 = fmaf(s0, va.z, va.w);
            float xb0 = fmaf(s1, vb.x, vb.y), xb1 = fmaf(s1, vb.z, vb.w);
            float ya0 = __fdividef(1.f, 1.f + __expf(-xa0));
            float ya1 = __fdividef(1.f, 1.f + __expf(-xa1));
            float yb0 = __fdividef(1.f, 1.f + __expf(-xb0));
            float yb1 = __fdividef(1.f, 1.f + __expf(-xb1));
            int j = jj * 2;
            *(float2*)&out[j * N + n0]       = make_float2(ya0, yb0);
            *(float2*)&out[(j + 1) * N + n0] = make_float2(ya1, yb1);
        }
    } else {
        #pragma unroll 8
        for (int jj = 0; jj < EMB / 2; jj++) {
            float4 va = __ldg(&r0[jj]);
            float xa0 = fmaf(s0, va.x, va.y), xa1 = fmaf(s0, va.z, va.w);
            int j = jj * 2;
            out[j * N + n0]       = __fdividef(1.f, 1.f + __expf(-xa0));
            out[(j + 1) * N + n0] = __fdividef(1.f, 1.f + __expf(-xa1));
        }
    }
}

// ---------------- launch ------------------------------------------------------
extern "C" void kernel_launch(void* const* d_in, const int* in_sizes, int n_in,
                              void* d_out, int out_size) {
    const void*  edges = d_in[0];
    const float* W1    = (const float*)d_in[1];
    const float* b1    = (const float*)d_in[2];
    const float* W2    = (const float*)d_in[3];
    const float* b2    = (const float*)d_in[4];
    int E = in_sizes[0] / 2;
    int N = out_size / EMB;
    if (N > NMAX) N = NMAX;

    const int TB = 256;
    int gN = (N + TB - 1) / TB;
    int gE = (E + TB * 8 - 1) / (TB * 8);
    int gO = (N + TB * 2 - 1) / (TB * 2);

    k_init<<<gN + 1, TB>>>(edges, W1, b1, N);
    k_deg <<<gE, TB>>>(edges, E);
    k_dis <<<gN, TB>>>(N);
    k_tab <<<HID + 1, EMB>>>(W1, b1, W2, b2);
    k_scat<<<gE, TB>>>(edges, E);
    k_out <<<gO, TB>>>((float*)d_out, N);
}

// round 5
// speedup vs baseline: 1.1356x; 1.1356x over previous
#include <cuda_runtime.h>

#define NMAX 100000
#define HID 256
#define EMB 128

#define QS 65535.0f
#define QI 1.5259021896696422e-05f   // 1/65535

// ---------------- scratch (static device globals; no allocation) -------------
__device__ int            g_degi[NMAX];            // degree incl. self loop
__device__ unsigned short g_disq[NMAX];            // dis quantized to u16 (scale 65535)
__device__ unsigned int   g_tq[NMAX];              // integer sum of quantized dis[src]
__device__ float          g_thr[HID];              // sorted relu breakpoints
__device__ int            g_sidx[HID];             // permutation: sorted pos -> h
__device__ __align__(16) float2 g_tab[(HID + 1) * EMB]; // per-interval (A, C)
__device__ int            g_e32;                   // 1 if edge_index is int32-packed

// ---- K1: init deg/tq; last block: detect edge dtype + sort relu thresholds --
__global__ void k_init(const void* __restrict__ edges,
                       const float* __restrict__ W1, const float* __restrict__ b1,
                       int N) {
    if (blockIdx.x == gridDim.x - 1) {
        int t = threadIdx.x;
        if (t == 0) {
            const long long* p = (const long long*)edges;
            int is32 = 0;
            #pragma unroll
            for (int i = 0; i < 4; i++)
                if ((unsigned long long)p[i] >= (1ull << 32)) is32 = 1;
            g_e32 = is32;
        }
        // relu(s*w+b) crossing for s>0: thr=-b/w if (w>0,b<0) or (w<0,b>0)
        __shared__ float key[HID];
        __shared__ int   idx[HID];
        float w = W1[t], b = b1[t];
        float thr = 3.0e38f;
        if ((w > 0.f && b < 0.f) || (w < 0.f && b > 0.f)) thr = -b / w;
        key[t] = thr; idx[t] = t;
        __syncthreads();
        for (int k = 2; k <= HID; k <<= 1) {
            for (int j = k >> 1; j > 0; j >>= 1) {
                int p = t ^ j;
                if (p > t) {
                    bool up = ((t & k) == 0);
                    float ka = key[t], kb = key[p];
                    if ((ka > kb) == up) {
                        key[t] = kb; key[p] = ka;
                        int ia = idx[t]; idx[t] = idx[p]; idx[p] = ia;
                    }
                }
                __syncthreads();
            }
        }
        g_thr[t] = key[t];
        g_sidx[t] = idx[t];
    } else {
        int n = blockIdx.x * blockDim.x + threadIdx.x;
        if (n < N) { g_degi[n] = 1; g_tq[n] = 0u; }
    }
}

// ---- K2: degree over dst (8 edges / thread, streaming int4 loads) -----------
__global__ void k_deg(const void* __restrict__ edges, int E) {
    int i = (blockIdx.x * blockDim.x + threadIdx.x) * 8;
    if (i >= E) return;
    if (g_e32) {
        const int* p = (const int*)edges + E;  // dst half
        if (i + 8 <= E) {
            const int4* q = (const int4*)(p + i);
            int4 a = __ldcs(q);
            int4 b = __ldcs(q + 1);
            atomicAdd(&g_degi[a.x], 1); atomicAdd(&g_degi[a.y], 1);
            atomicAdd(&g_degi[a.z], 1); atomicAdd(&g_degi[a.w], 1);
            atomicAdd(&g_degi[b.x], 1); atomicAdd(&g_degi[b.y], 1);
            atomicAdd(&g_degi[b.z], 1); atomicAdd(&g_degi[b.w], 1);
        } else {
            for (int j = i; j < E; j++) atomicAdd(&g_degi[p[j]], 1);
        }
    } else {
        const long long* p = (const long long*)edges + E;
        if (i + 8 <= E) {
            const int4* q = (const int4*)(p + i);
            int4 a = __ldcs(q), b = __ldcs(q + 1), c = __ldcs(q + 2), d = __ldcs(q + 3);
            atomicAdd(&g_degi[a.x], 1); atomicAdd(&g_degi[a.z], 1);
            atomicAdd(&g_degi[b.x], 1); atomicAdd(&g_degi[b.z], 1);
            atomicAdd(&g_degi[c.x], 1); atomicAdd(&g_degi[c.z], 1);
            atomicAdd(&g_degi[d.x], 1); atomicAdd(&g_degi[d.z], 1);
        } else {
            for (int j = i; j < E; j++) atomicAdd(&g_degi[(int)p[j]], 1);
        }
    }
}

// ---- K3: quantize dis to u16 (L1-resident gather table for k_scat) ----------
__global__ void k_dis(int N) {
    int n = blockIdx.x * blockDim.x + threadIdx.x;
    if (n < N)
        g_disq[n] = (unsigned short)__float2uint_rn(rsqrtf((float)g_degi[n]) * QS);
}

// ---- K4: build tables via base + delta prefix-scan ---------------------------
// One block per output column j (128 blocks x 256 threads). Thread t provides:
//   base term of unit h=t (active as s->0+), and the delta of the t-th sorted
//   breakpoint (toggled term is exactly 0 at its breakpoint => value-exact).
// Block reduction gives the base; inclusive scan gives all 257 intervals.
__global__ void k_tab(const float* __restrict__ W1, const float* __restrict__ b1,
                      const float* __restrict__ W2, const float* __restrict__ b2) {
    __shared__ float sa[HID], sc[HID];  // deltas -> scan
    __shared__ float ra[HID], rc[HID];  // base terms -> reduction
    int j = blockIdx.x;
    int t = threadIdx.x;

    // base term (h = t)
    float w = W1[t], b = b1[t];
    float w2 = __ldg(&W2[t * EMB + j]);
    bool act = (b > 0.f) || (b == 0.f && w > 0.f);
    ra[t] = act ? w * w2 : 0.f;
    rc[t] = act ? b * w2 : 0.f;

    // delta term (sorted position t)
    int h = g_sidx[t];
    float wh = W1[h], bh = b1[h];
    float w2h = __ldg(&W2[h * EMB + j]);
    float d = (wh > 0.f && bh < 0.f) ? 1.f : ((wh < 0.f && bh > 0.f) ? -1.f : 0.f);
    sa[t] = d * wh * w2h;
    sc[t] = d * bh * w2h;
    __syncthreads();

    // block reduction of base
    #pragma unroll
    for (int s = HID / 2; s > 0; s >>= 1) {
        if (t < s) { ra[t] += ra[t + s]; rc[t] += rc[t + s]; }
        __syncthreads();
    }
    float A0 = ra[0];
    float C0 = rc[0] + b2[j];

    // inclusive Hillis-Steele scan of deltas
    #pragma unroll
    for (int off = 1; off < HID; off <<= 1) {
        float va = 0.f, vc = 0.f;
        if (t >= off) { va = sa[t - off]; vc = sc[t - off]; }
        __syncthreads();
        if (t >= off) { sa[t] += va; sc[t] += vc; }
        __syncthreads();
    }

    if (t == 0) g_tab[j] = make_float2(A0, C0);
    g_tab[(t + 1) * EMB + j] = make_float2(A0 + sa[t], C0 + sc[t]);
}

// ---- K5: tq[dst] += disq[src]  (u16 L1 gather + u32 L2 atomic, no float) ----
__device__ __forceinline__ void scat1(int src, int dst) {
    unsigned int q = (unsigned int)__ldg(&g_disq[src]);
    atomicAdd(&g_tq[dst], q);
}
__global__ void k_scat(const void* __restrict__ edges, int E) {
    int i = (blockIdx.x * blockDim.x + threadIdx.x) * 8;
    if (i >= E) return;
    if (g_e32) {
        const int* ps = (const int*)edges;
        const int* pd = ps + E;
        if (i + 8 <= E) {
            const int4* qs = (const int4*)(ps + i);
            const int4* qd = (const int4*)(pd + i);
            int4 s0 = __ldcs(qs), s1 = __ldcs(qs + 1);
            int4 d0 = __ldcs(qd), d1 = __ldcs(qd + 1);
            scat1(s0.x, d0.x); scat1(s0.y, d0.y); scat1(s0.z, d0.z); scat1(s0.w, d0.w);
            scat1(s1.x, d1.x); scat1(s1.y, d1.y); scat1(s1.z, d1.z); scat1(s1.w, d1.w);
        } else {
            for (int j = i; j < E; j++) scat1(ps[j], pd[j]);
        }
    } else {
        const long long* ps = (const long long*)edges;
        const long long* pd = ps + E;
        if (i + 8 <= E) {
            const int4* qs = (const int4*)(ps + i);
            const int4* qd = (const int4*)(pd + i);
            int4 s0 = __ldcs(qs), s1 = __ldcs(qs + 1), s2 = __ldcs(qs + 2), s3 = __ldcs(qs + 3);
            int4 d0 = __ldcs(qd), d1 = __ldcs(qd + 1), d2 = __ldcs(qd + 2), d3 = __ldcs(qd + 3);
            scat1(s0.x, d0.x); scat1(s0.z, d0.z);
            scat1(s1.x, d1.x); scat1(s1.z, d1.z);
            scat1(s2.x, d2.x); scat1(s2.z, d2.z);
            scat1(s3.x, d3.x); scat1(s3.z, d3.z);
        } else {
            for (int j = i; j < E; j++) scat1((int)ps[j], (int)pd[j]);
        }
    }
}

// ---- K6: per-node s + binary search + 128 affine sigmoids (2 nodes/thread) --
__global__ void k_out(float* __restrict__ out, int N) {
    __shared__ float sthr[HID];
    for (int i = threadIdx.x; i < HID; i += blockDim.x) sthr[i] = g_thr[i];
    __syncthreads();

    int n0 = (blockIdx.x * blockDim.x + threadIdx.x) * 2;
    if (n0 >= N) return;
    bool has2 = (n0 + 1 < N) && ((N & 1) == 0);
    int n1 = has2 ? n0 + 1 : n0;

    float d0 = rsqrtf((float)g_degi[n0]);
    float d1 = rsqrtf((float)g_degi[n1]);
    float s0 = d0 * ((float)g_tq[n0] * QI + d0);
    float s1 = d1 * ((float)g_tq[n1] * QI + d1);

    int lo0 = 0, hi0 = HID, lo1 = 0, hi1 = HID;
    #pragma unroll
    for (int it = 0; it < 8; it++) {
        int m0 = (lo0 + hi0) >> 1;
        if (sthr[m0] < s0) lo0 = m0 + 1; else hi0 = m0;
        int m1 = (lo1 + hi1) >> 1;
        if (sthr[m1] < s1) lo1 = m1 + 1; else hi1 = m1;
    }

    const float4* __restrict__ r0 = (const float4*)(g_tab + lo0 * EMB);
    const float4* __restrict__ r1 = (const float4*)(g_tab + lo1 * EMB);

    if (has2) {
        #pragma unroll 8
        for (int jj = 0; jj < EMB / 2; jj++) {
            float4 va = __ldg(&r0[jj]);
            float4 vb = __ldg(&r1[jj]);
            float xa0 = fmaf(s0, va.x, va.y), xa1 = fmaf(s0, va.z, va.w);
            float xb0 = fmaf(s1, vb.x, vb.y), xb1 = fmaf(s1, vb.z, vb.w);
            float ya0 = __fdividef(1.f, 1.f + __expf(-xa0));
            float ya1 = __fdividef(1.f, 1.f + __expf(-xa1));
            float yb0 = __fdividef(1.f, 1.f + __expf(-xb0));
            float yb1 = __fdividef(1.f, 1.f + __expf(-xb1));
            int j = jj * 2;
            *(float2*)&out[j * N + n0]       = make_float2(ya0, yb0);
            *(float2*)&out[(j + 1) * N + n0] = make_float2(ya1, yb1);
        }
    } else {
        #pragma unroll 8
        for (int jj = 0; jj < EMB / 2; jj++) {
            float4 va = __ldg(&r0[jj]);
            float xa0 = fmaf(s0, va.x, va.y), xa1 = fmaf(s0, va.z, va.w);
            int j = jj * 2;
            out[j * N + n0]       = __fdividef(1.f, 1.f + __expf(-xa0));
            out[(j + 1) * N + n0] = __fdividef(1.f, 1.f + __expf(-xa1));
        }
    }
}

// ---------------- launch ------------------------------------------------------
extern "C" void kernel_launch(void* const* d_in, const int* in_sizes, int n_in,
                              void* d_out, int out_size) {
    const void*  edges = d_in[0];
    const float* W1    = (const float*)d_in[1];
    const float* b1    = (const float*)d_in[2];
    const float* W2    = (const float*)d_in[3];
    const float* b2    = (const float*)d_in[4];
    int E = in_sizes[0] / 2;
    int N = out_size / EMB;
    if (N > NMAX) N = NMAX;

    const int TB = 256;
    int gN = (N + TB - 1) / TB;
    int gE = (E + TB * 8 - 1) / (TB * 8);
    int gO = (N + TB * 2 - 1) / (TB * 2);

    k_init<<<gN + 1, TB>>>(edges, W1, b1, N);
    k_deg <<<gE, TB>>>(edges, E);
    k_dis <<<gN, TB>>>(N);
    k_tab <<<EMB, HID>>>(W1, b1, W2, b2);
    k_scat<<<gE, TB>>>(edges, E);
    k_out <<<gO, TB>>>((float*)d_out, N);
}